// round 7
// baseline (speedup 1.0000x reference)
#include <cuda_runtime.h>

#define Bb 8
#define Nn 64
#define Kk 64
#define Tt 128
#define NB1 65
#define KK2 4096
#define MAXROWS 512
#define SSTR 68
#define SMEM_BYTES (2 * 128 * SSTR * 4)   // 69632 -> 3 CTAs/SM
#define CSTR 32
#define NLVL 16                           // distributed level-flag copies

typedef unsigned long long ull;

__device__ __align__(256) float g_chart[NB1 * NB1 * Bb * Kk];
__device__ __align__(256) float g_pair3[3][MAXROWS * KK2];
__device__ __align__(256) float g_part[32 * MAXROWS * Kk];

__device__ int g_lvl[NLVL * CSTR];         // distributed level_done copies
__device__ int g_pre_ready[NB1 * 8 * CSTR];
__device__ int g_chunk_done[NB1 * 8 * CSTR];
__device__ int g_red_tile [NB1 * 8 * CSTR];
__device__ int g_tiles_done[NB1 * CSTR];
__device__ int g_c0[8 * CSTR];
__device__ int g_c0m;
__device__ unsigned g_arrive = 0;
__device__ unsigned g_release = 0;

__device__ __forceinline__ int cidx(int i, int j, int b, int k) {
    return ((i * NB1 + j) * Bb + b) * Kk + k;
}
__device__ __forceinline__ ull pack2(float lo, float hi) {
    ull r; asm("mov.b64 %0, {%1, %2};" : "=l"(r) : "f"(lo), "f"(hi)); return r;
}
__device__ __forceinline__ void fma2(ull& d, ull a, ull b) {
    asm("fma.rn.f32x2 %0, %1, %2, %0;" : "+l"(d) : "l"(a), "l"(b));
}
__device__ __forceinline__ float2 unpk(ull v) {
    float2 o; asm("mov.b64 {%0, %1}, %2;" : "=f"(o.x), "=f"(o.y) : "l"(v)); return o;
}
__device__ __forceinline__ int ld_acq(const int* p) {
    int v; asm volatile("ld.acquire.gpu.global.b32 %0, [%1];" : "=r"(v) : "l"(p) : "memory"); return v;
}
__device__ __forceinline__ void red_rel(int* p, int v) {
    asm volatile("red.release.gpu.global.add.s32 [%0], %1;" :: "l"(p), "r"(v) : "memory");
}
__device__ __forceinline__ int atom_ar(int* p, int v) {
    int o; asm volatile("atom.acq_rel.gpu.global.add.s32 %0, [%1], %2;" : "=r"(o) : "l"(p), "r"(v) : "memory"); return o;
}
__device__ __forceinline__ void st_rel(int* p, int v) {
    asm volatile("st.release.gpu.global.b32 [%0], %1;" :: "l"(p), "r"(v) : "memory");
}
__device__ __forceinline__ void publish_level(int s) {
    #pragma unroll
    for (int i = 0; i < NLVL; i++) st_rel(&g_lvl[i * CSTR], s);
}
__device__ __forceinline__ void spin_slot(int slot, int target) {
    if (threadIdx.x == 0) {
        while (ld_acq(&g_lvl[slot * CSTR]) < target) { }
    }
    __syncthreads();
}
__device__ __forceinline__ void spin_ctr(int* p, int target) {
    if (threadIdx.x == 0) {
        while (ld_acq(p) < target) { }
    }
    __syncthreads();
}
__device__ __forceinline__ void gbar(unsigned target, int nblk) {
    __threadfence();
    __syncthreads();
    if (threadIdx.x == 0) {
        unsigned old = atomicAdd(&g_arrive, 1u);
        if (old == (unsigned)(nblk - 1)) {
            g_arrive = 0;
            __threadfence();
            *(volatile unsigned*)&g_release = target;
        } else {
            while ((int)(*(volatile unsigned*)&g_release - target) < 0) __nanosleep(64);
            __threadfence();
        }
    }
    __syncthreads();
}

__global__ void __launch_bounds__(256, 3)
rbn_persistent(const float* __restrict__ seq, const float* __restrict__ rule,
               const float* __restrict__ emit, const float* __restrict__ prior,
               float* __restrict__ out, int nblk)
{
    extern __shared__ float smem[];
    float* sA = smem;
    float* sB = smem + 128 * SSTR;

    const int tid = threadIdx.x;
    const int bid = blockIdx.x;
    const int w = tid >> 5, lane = tid & 31;
    const int tx = tid & 15, ty = tid >> 4;
    const int x0 = ty * 4, y0r = tx * 4;
    const int myslot = bid & (NLVL - 1);

    const unsigned gen = *(volatile unsigned*)&g_release;

    // ---- Phase 0: span-1 cells (distributed completion counters)
    for (int u = bid; u < Nn * Bb; u += nblk) {
        int i = u >> 3, b = u & 7;
        const float* srow = seq + (b * Nn + i) * Tt;
        #pragma unroll
        for (int aa = 0; aa < 8; aa++) {
            int a = w * 8 + aa;
            float p = 0.f;
            #pragma unroll
            for (int q = 0; q < 4; q++) {
                int t2 = lane + q * 32;
                p += emit[a * Tt + t2] * srow[t2];
            }
            #pragma unroll
            for (int off = 16; off; off >>= 1) p += __shfl_down_sync(0xffffffffu, p, off);
            if (lane == 0) g_chart[cidx(i, i + 1, b, a)] = p;
        }
        __syncthreads();
        if (tid == 0) {
            int old = atom_ar(&g_c0[(u & 7) * CSTR], 1);
            if (old == (Nn * Bb / 8) - 1) {
                int mo = atom_ar(&g_c0m, 1);
                if (mo == 7) publish_level(1);
            }
        }
    }

    for (int s = 2; s <= Nn; s++) {
        const int m = Nn - s + 1;
        const int rows = m * Bb;
        const int ntiles = (rows + 63) >> 6;
        const bool modeB = (rows <= 256);
        const int nch = modeB ? 64 : 32;
        const int ck  = modeB ? 64 : 128;
        const int nunits = ntiles * nch;
        float* const pairc = g_pair3[s % 3];

        const int lr = tid >> 2, lq = tid & 3;

        if (bid < nunits) {
            const int tile  = modeB ? (bid >> 6) : (bid >> 5);
            const int chunk = modeB ? (bid & 63) : (bid & 31);
            const int kbase = chunk * ck;
            const int R_t = min(64, rows - tile * 64);

            // prefetch rule slice into sB before any gate
            {
                const float4* pb = (const float4*)&rule[(size_t)lr * KK2 + kbase + lq * 4];
                for (int kb = 0; kb < ck; kb += 16) {
                    float4 vb = pb[kb >> 2];
                    int kk = kb + lq * 4;
                    sB[(kk + 0) * SSTR + lr] = vb.x;
                    sB[(kk + 1) * SSTR + lr] = vb.y;
                    sB[(kk + 2) * SSTR + lr] = vb.z;
                    sB[(kk + 3) * SSTR + lr] = vb.w;
                }
            }
            spin_slot(myslot, s - 1);
            if (s >= 6) spin_ctr(&g_pre_ready[(s * 8 + tile) * CSTR], R_t);

            // ---- fused stage: sA = pairc(A_pre, splits 3..s-3... see gates) + inline splits
            {
                const int row = tile * 64 + lr;
                const int cell = row >> 3, b = row & 7;
                const float* L1 = &g_chart[cidx(cell, cell + 1, b, 0)];
                const float* R1 = &g_chart[cidx(cell + 1, cell + s, b, 0)];
                const float* L2 = &g_chart[cidx(cell, cell + s - 1, b, 0)];
                const float* R2 = &g_chart[cidx(cell + s - 1, cell + s, b, 0)];
                const float* L3 = &g_chart[cidx(cell, cell + 2, b, 0)];
                const float* R3 = &g_chart[cidx(cell + 2, cell + s, b, 0)];
                const float* L4 = &g_chart[cidx(cell, cell + s - 2, b, 0)];
                const float* R4 = &g_chart[cidx(cell + s - 2, cell + s, b, 0)];
                const float4* pa = (const float4*)&pairc[(size_t)row * KK2 + kbase + lq * 4];
                for (int kb = 0; kb < ck; kb += 16) {
                    const int kk = kb + lq * 4;
                    const int kg = kbase + kk;
                    const int xx = kg >> 6, yy = kg & 63;
                    float4 va;
                    if (s >= 6) va = __ldcg(pa + (kb >> 2));
                    else { va.x = 0.f; va.y = 0.f; va.z = 0.f; va.w = 0.f; }
                    {
                        float l1 = __ldcg(L1 + xx);
                        float4 r1 = __ldcg((const float4*)(R1 + yy));
                        va.x += l1 * r1.x; va.y += l1 * r1.y;
                        va.z += l1 * r1.z; va.w += l1 * r1.w;
                    }
                    if (s >= 3) {
                        float l2 = __ldcg(L2 + xx);
                        float4 r2 = __ldcg((const float4*)(R2 + yy));
                        va.x += l2 * r2.x; va.y += l2 * r2.y;
                        va.z += l2 * r2.z; va.w += l2 * r2.w;
                    }
                    if (s >= 4) {
                        float l3 = __ldcg(L3 + xx);
                        float4 r3 = __ldcg((const float4*)(R3 + yy));
                        va.x += l3 * r3.x; va.y += l3 * r3.y;
                        va.z += l3 * r3.z; va.w += l3 * r3.w;
                    }
                    if (s >= 5) {
                        float l4 = __ldcg(L4 + xx);
                        float4 r4 = __ldcg((const float4*)(R4 + yy));
                        va.x += l4 * r4.x; va.y += l4 * r4.y;
                        va.z += l4 * r4.z; va.w += l4 * r4.w;
                    }
                    sA[(kk + 0) * SSTR + lr] = va.x;
                    sA[(kk + 1) * SSTR + lr] = va.y;
                    sA[(kk + 2) * SSTR + lr] = va.z;
                    sA[(kk + 3) * SSTR + lr] = va.w;
                }
            }
            __syncthreads();

            // ---- GEMM 64x64 x ck
            ull acc[4][2];
            #pragma unroll
            for (int i = 0; i < 4; i++) { acc[i][0] = 0ull; acc[i][1] = 0ull; }
            #pragma unroll 8
            for (int k = 0; k < ck; k++) {
                float4 av = *(const float4*)&sA[k * SSTR + x0];
                float4 bv = *(const float4*)&sB[k * SSTR + y0r];
                ull b01 = pack2(bv.x, bv.y), b23 = pack2(bv.z, bv.w);
                ull a2;
                a2 = pack2(av.x, av.x); fma2(acc[0][0], a2, b01); fma2(acc[0][1], a2, b23);
                a2 = pack2(av.y, av.y); fma2(acc[1][0], a2, b01); fma2(acc[1][1], a2, b23);
                a2 = pack2(av.z, av.z); fma2(acc[2][0], a2, b01); fma2(acc[2][1], a2, b23);
                a2 = pack2(av.w, av.w); fma2(acc[3][0], a2, b01); fma2(acc[3][1], a2, b23);
            }
            #pragma unroll
            for (int i = 0; i < 4; i++) {
                int row = tile * 64 + x0 + i;
                int base = modeB ? ((chunk << 8) + row) : ((chunk << 9) + row);
                float2 e0 = unpk(acc[i][0]), e1 = unpk(acc[i][1]);
                float4 o; o.x = e0.x; o.y = e0.y; o.z = e1.x; o.w = e1.y;
                *(float4*)&g_part[(size_t)base * Kk + y0r] = o;
            }
            __syncthreads();
            if (tid == 0) red_rel(&g_chunk_done[(s * 8 + tile) * CSTR], 1);

            // ---- fused deterministic reduction
            spin_ctr(&g_chunk_done[(s * 8 + tile) * CSTR], nch);
            if (modeB) {
                if (tid < 64 && chunk < R_t) {
                    int row = tile * 64 + chunk, a = tid;
                    float ssum = 0.f;
                    #pragma unroll 16
                    for (int cc = 0; cc < 64; cc++)
                        ssum += __ldcg(&g_part[(size_t)((cc << 8) + row) * Kk + a]);
                    int cell = row >> 3, b = row & 7;
                    g_chart[cidx(cell, cell + s, b, a)] = ssum;
                }
            } else {
                if (tid < 128) {
                    int rl = chunk * 2 + (tid >> 6);
                    if (rl < R_t) {
                        int row = tile * 64 + rl, a = tid & 63;
                        float ssum = 0.f;
                        #pragma unroll 16
                        for (int cc = 0; cc < 32; cc++)
                            ssum += __ldcg(&g_part[(size_t)((cc << 9) + row) * Kk + a]);
                        int cell = row >> 3, b = row & 7;
                        g_chart[cidx(cell, cell + s, b, a)] = ssum;
                    }
                }
            }
            __syncthreads();
            if (tid == 0) {
                int old = atom_ar(&g_red_tile[(s * 8 + tile) * CSTR], 1);
                if (old == nch - 1) {
                    int t = atom_ar(&g_tiles_done[s * CSTR], 1);
                    if (t == ntiles - 1) publish_level(s);
                }
            }
        }

        // ---- A_pre(s+1): splits 3..s-2, gated on level s-2 (already done) -> pair3[(s+1)%3]
        if (s < Nn && s + 1 >= 6) {
            const int s2 = s + 1;
            const int rows2 = (Nn - s2 + 1) * Bb;
            float* const pairn = g_pair3[s2 % 3];
            spin_slot(myslot, s2 - 3);
            for (int u = bid; u < rows2; u += nblk) {
                const int cell = u >> 3, b = u & 7;
                ull acc[4][2];
                #pragma unroll
                for (int i = 0; i < 4; i++) { acc[i][0] = 0ull; acc[i][1] = 0ull; }
                const float* Lbase = &g_chart[cidx(cell, cell, b, x0)];
                const float* Rbase = &g_chart[cidx(cell, cell + s2, b, y0r)];
                #pragma unroll 4
                for (int sp = 3; sp <= s2 - 3; sp++) {
                    float4 L = __ldcg((const float4*)(Lbase + (size_t)sp * (Bb * Kk)));
                    float4 R = __ldcg((const float4*)(Rbase + (size_t)sp * (NB1 * Bb * Kk)));
                    ull r01 = pack2(R.x, R.y), r23 = pack2(R.z, R.w);
                    ull l;
                    l = pack2(L.x, L.x); fma2(acc[0][0], l, r01); fma2(acc[0][1], l, r23);
                    l = pack2(L.y, L.y); fma2(acc[1][0], l, r01); fma2(acc[1][1], l, r23);
                    l = pack2(L.z, L.z); fma2(acc[2][0], l, r01); fma2(acc[2][1], l, r23);
                    l = pack2(L.w, L.w); fma2(acc[3][0], l, r01); fma2(acc[3][1], l, r23);
                }
                #pragma unroll
                for (int i = 0; i < 4; i++) {
                    float2 e0 = unpk(acc[i][0]), e1 = unpk(acc[i][1]);
                    float4 o; o.x = e0.x; o.y = e0.y; o.z = e1.x; o.w = e1.y;
                    *(float4*)&pairn[(size_t)u * KK2 + (x0 + i) * Kk + y0r] = o;
                }
                __syncthreads();
                if (tid == 0) red_rel(&g_pre_ready[(s2 * 8 + (u >> 6)) * CSTR], 1);
            }
        }
    }

    // ---- Final output
    if (bid == 0) {
        spin_slot(0, Nn);
        if (w < Bb) {
            const int b = w;
            float p = 0.f;
            #pragma unroll
            for (int q = 0; q < 2; q++) {
                int a = lane + q * 32;
                p += prior[a] * __ldcg(&g_chart[cidx(0, Nn, b, a)]);
            }
            #pragma unroll
            for (int off = 16; off; off >>= 1) p += __shfl_down_sync(0xffffffffu, p, off);
            if (lane == 0) out[b] = p;
        }
    }

    // ---- End barrier + reset for next replay
    gbar(gen + 1, nblk);
    if (bid == 0) {
        for (int i = tid; i < NB1 * 8 * CSTR; i += 256) {
            g_pre_ready[i] = 0;
            g_chunk_done[i] = 0;
            g_red_tile[i] = 0;
        }
        for (int i = tid; i < NB1 * CSTR; i += 256) g_tiles_done[i] = 0;
        for (int i = tid; i < NLVL * CSTR; i += 256) g_lvl[i] = 0;
        for (int i = tid; i < 8 * CSTR; i += 256) g_c0[i] = 0;
        if (tid == 0) g_c0m = 0;
    }
}

extern "C" void kernel_launch(void* const* d_in, const int* in_sizes, int n_in,
                              void* d_out, int out_size)
{
    const float* seq   = (const float*)d_in[0];
    const float* rule  = (const float*)d_in[1];
    const float* emit  = (const float*)d_in[2];
    const float* prior = (const float*)d_in[3];
    float* out = (float*)d_out;

    cudaFuncSetAttribute(rbn_persistent, cudaFuncAttributeMaxDynamicSharedMemorySize, SMEM_BYTES);

    int dev = 0, nsm = 1;
    cudaGetDevice(&dev);
    cudaDeviceGetAttribute(&nsm, cudaDevAttrMultiProcessorCount, dev);
    int bpm = 1;
    cudaOccupancyMaxActiveBlocksPerMultiprocessor(&bpm, rbn_persistent, 256, SMEM_BYTES);
    if (bpm < 1) bpm = 1;
    if (bpm > 3) bpm = 3;
    int nblk = nsm * bpm;
    if (nblk > 444) nblk = 444;
    if (nblk < 256) nblk = 256;

    rbn_persistent<<<nblk, 256, SMEM_BYTES>>>(seq, rule, emit, prior, out, nblk);
}

// round 8
// speedup vs baseline: 1.1992x; 1.1992x over previous
#include <cuda_runtime.h>

#define Bb 8
#define Nn 64
#define Kk 64
#define Tt 128
#define NB1 65
#define KK2 4096
#define MAXROWS 512
#define SSTR 68
#define SMEM_BYTES (2 * 128 * SSTR * 4)   // 69632 -> 3 CTAs/SM
#define CSTR 32
#define NLVL 16

typedef unsigned long long ull;

__device__ __align__(256) float g_chart[NB1 * NB1 * Bb * Kk];
__device__ __align__(256) float g_pair2[2][MAXROWS * KK2];
__device__ __align__(256) float g_part[32 * MAXROWS * Kk];

__device__ int g_lvl[NLVL * CSTR];
__device__ int g_pre_ready[NB1 * 8 * CSTR];
__device__ int g_chunk_done[NB1 * 8 * CSTR];
__device__ int g_red_tile [NB1 * 8 * CSTR];
__device__ int g_tiles_done[NB1 * CSTR];
__device__ int g_c0[8 * CSTR];
__device__ int g_c0m;
__device__ unsigned g_arrive = 0;
__device__ unsigned g_release = 0;

__device__ __forceinline__ int cidx(int i, int j, int b, int k) {
    return ((i * NB1 + j) * Bb + b) * Kk + k;
}
__device__ __forceinline__ ull pack2(float lo, float hi) {
    ull r; asm("mov.b64 %0, {%1, %2};" : "=l"(r) : "f"(lo), "f"(hi)); return r;
}
__device__ __forceinline__ void fma2(ull& d, ull a, ull b) {
    asm("fma.rn.f32x2 %0, %1, %2, %0;" : "+l"(d) : "l"(a), "l"(b));
}
__device__ __forceinline__ float2 unpk(ull v) {
    float2 o; asm("mov.b64 {%0, %1}, %2;" : "=f"(o.x), "=f"(o.y) : "l"(v)); return o;
}
__device__ __forceinline__ int ld_acq(const int* p) {
    int v; asm volatile("ld.acquire.gpu.global.b32 %0, [%1];" : "=r"(v) : "l"(p) : "memory"); return v;
}
__device__ __forceinline__ void red_rel(int* p, int v) {
    asm volatile("red.release.gpu.global.add.s32 [%0], %1;" :: "l"(p), "r"(v) : "memory");
}
__device__ __forceinline__ int atom_ar(int* p, int v) {
    int o; asm volatile("atom.acq_rel.gpu.global.add.s32 %0, [%1], %2;" : "=r"(o) : "l"(p), "r"(v) : "memory"); return o;
}
__device__ __forceinline__ void st_rel(int* p, int v) {
    asm volatile("st.release.gpu.global.b32 [%0], %1;" :: "l"(p), "r"(v) : "memory");
}
__device__ __forceinline__ void publish_level(int s) {
    #pragma unroll
    for (int i = 0; i < NLVL; i++) st_rel(&g_lvl[i * CSTR], s);
}
__device__ __forceinline__ void spin_level(int slot, int target) {
    if (threadIdx.x == 0) {
        while (ld_acq(&g_lvl[slot * CSTR]) < target) __nanosleep(32);
    }
    __syncthreads();
}
__device__ __forceinline__ void spin_ctr(int* p, int target) {
    if (threadIdx.x == 0) {
        while (ld_acq(p) < target) __nanosleep(32);
    }
    __syncthreads();
}
__device__ __forceinline__ void gbar(unsigned target, int nblk) {
    __threadfence();
    __syncthreads();
    if (threadIdx.x == 0) {
        unsigned old = atomicAdd(&g_arrive, 1u);
        if (old == (unsigned)(nblk - 1)) {
            g_arrive = 0;
            __threadfence();
            *(volatile unsigned*)&g_release = target;
        } else {
            while ((int)(*(volatile unsigned*)&g_release - target) < 0) __nanosleep(64);
            __threadfence();
        }
    }
    __syncthreads();
}

__global__ void __launch_bounds__(256, 3)
rbn_persistent(const float* __restrict__ seq, const float* __restrict__ rule,
               const float* __restrict__ emit, const float* __restrict__ prior,
               float* __restrict__ out, int nblk)
{
    extern __shared__ float smem[];
    float* sA = smem;
    float* sB = smem + 128 * SSTR;

    const int tid = threadIdx.x;
    const int bid = blockIdx.x;
    const int w = tid >> 5, lane = tid & 31;
    const int tx = tid & 15, ty = tid >> 4;
    const int x0 = ty * 4, y0r = tx * 4;
    const int myslot = bid & (NLVL - 1);

    const unsigned gen = *(volatile unsigned*)&g_release;

    // ---- Phase 0: span-1 cells (distributed completion counters)
    for (int u = bid; u < Nn * Bb; u += nblk) {
        int i = u >> 3, b = u & 7;
        const float* srow = seq + (b * Nn + i) * Tt;
        #pragma unroll
        for (int aa = 0; aa < 8; aa++) {
            int a = w * 8 + aa;
            float p = 0.f;
            #pragma unroll
            for (int q = 0; q < 4; q++) {
                int t2 = lane + q * 32;
                p += emit[a * Tt + t2] * srow[t2];
            }
            #pragma unroll
            for (int off = 16; off; off >>= 1) p += __shfl_down_sync(0xffffffffu, p, off);
            if (lane == 0) g_chart[cidx(i, i + 1, b, a)] = p;
        }
        __syncthreads();
        if (tid == 0) {
            int old = atom_ar(&g_c0[(u & 7) * CSTR], 1);
            if (old == (Nn * Bb / 8) - 1) {
                int mo = atom_ar(&g_c0m, 1);
                if (mo == 7) publish_level(1);
            }
        }
    }

    for (int s = 2; s <= Nn; s++) {
        const int m = Nn - s + 1;
        const int rows = m * Bb;
        const int ntiles = (rows + 63) >> 6;
        const bool modeB = (rows <= 256);
        const int nch = modeB ? 64 : 32;
        const int ck  = modeB ? 64 : 128;
        const int nunits = ntiles * nch;
        float* const pairc = g_pair2[s & 1];

        int tile = 0, chunk = 0, kbase = 0, R_t = 0;
        const int lr = tid >> 2, lq = tid & 3;
        if (bid < nunits) {
            tile  = modeB ? (bid >> 6) : (bid >> 5);
            chunk = modeB ? (bid & 63) : (bid & 31);
            kbase = chunk * ck;
            R_t = min(64, rows - tile * 64);
            // prefetch rule slice (constant data) before any gate
            const float4* pb = (const float4*)&rule[(size_t)lr * KK2 + kbase + lq * 4];
            for (int kb = 0; kb < ck; kb += 16) {
                float4 vb = pb[kb >> 2];
                int kk = kb + lq * 4;
                sB[(kk + 0) * SSTR + lr] = vb.x;
                sB[(kk + 1) * SSTR + lr] = vb.y;
                sB[(kk + 2) * SSTR + lr] = vb.z;
                sB[(kk + 3) * SSTR + lr] = vb.w;
            }
        }

        spin_level(myslot, s - 1);       // gates B's chart reads AND A_pre below

        if (bid < nunits) {
            if (s >= 4) spin_ctr(&g_pre_ready[(s * 8 + tile) * CSTR], R_t);

            // ---- stage sA = pairc + split{1} + split{s-1} (fused A_final)
            {
                const int row = tile * 64 + lr;
                const int cell = row >> 3, b = row & 7;
                const float* L1row = &g_chart[cidx(cell, cell + 1, b, 0)];
                const float* R1row = &g_chart[cidx(cell + 1, cell + s, b, 0)];
                const float* L2row = &g_chart[cidx(cell, cell + s - 1, b, 0)];
                const float* R2row = &g_chart[cidx(cell + s - 1, cell + s, b, 0)];
                const float4* pa = (const float4*)&pairc[(size_t)row * KK2 + kbase + lq * 4];
                for (int kb = 0; kb < ck; kb += 16) {
                    const int kk = kb + lq * 4;
                    const int kg = kbase + kk;
                    const int xx = kg >> 6, yy = kg & 63;
                    float4 va;
                    if (s >= 4) va = __ldcg(pa + (kb >> 2));
                    else { va.x = 0.f; va.y = 0.f; va.z = 0.f; va.w = 0.f; }
                    {
                        float l1 = __ldcg(L1row + xx);
                        float4 r1 = __ldcg((const float4*)(R1row + yy));
                        va.x += l1 * r1.x; va.y += l1 * r1.y;
                        va.z += l1 * r1.z; va.w += l1 * r1.w;
                    }
                    if (s >= 3) {
                        float l2 = __ldcg(L2row + xx);
                        float4 r2 = __ldcg((const float4*)(R2row + yy));
                        va.x += l2 * r2.x; va.y += l2 * r2.y;
                        va.z += l2 * r2.z; va.w += l2 * r2.w;
                    }
                    sA[(kk + 0) * SSTR + lr] = va.x;
                    sA[(kk + 1) * SSTR + lr] = va.y;
                    sA[(kk + 2) * SSTR + lr] = va.z;
                    sA[(kk + 3) * SSTR + lr] = va.w;
                }
            }
            __syncthreads();

            // ---- GEMM: 64x64 x ck
            ull acc[4][2];
            #pragma unroll
            for (int i = 0; i < 4; i++) { acc[i][0] = 0ull; acc[i][1] = 0ull; }
            #pragma unroll 8
            for (int k = 0; k < ck; k++) {
                float4 av = *(const float4*)&sA[k * SSTR + x0];
                float4 bv = *(const float4*)&sB[k * SSTR + y0r];
                ull b01 = pack2(bv.x, bv.y), b23 = pack2(bv.z, bv.w);
                ull a2;
                a2 = pack2(av.x, av.x); fma2(acc[0][0], a2, b01); fma2(acc[0][1], a2, b23);
                a2 = pack2(av.y, av.y); fma2(acc[1][0], a2, b01); fma2(acc[1][1], a2, b23);
                a2 = pack2(av.z, av.z); fma2(acc[2][0], a2, b01); fma2(acc[2][1], a2, b23);
                a2 = pack2(av.w, av.w); fma2(acc[3][0], a2, b01); fma2(acc[3][1], a2, b23);
            }
            #pragma unroll
            for (int i = 0; i < 4; i++) {
                int row = tile * 64 + x0 + i;
                int base = modeB ? ((chunk << 8) + row) : ((chunk << 9) + row);
                float2 e0 = unpk(acc[i][0]), e1 = unpk(acc[i][1]);
                float4 o; o.x = e0.x; o.y = e0.y; o.z = e1.x; o.w = e1.y;
                *(float4*)&g_part[(size_t)base * Kk + y0r] = o;
            }
            __syncthreads();
            if (tid == 0) red_rel(&g_chunk_done[(s * 8 + tile) * CSTR], 1);

            // ---- fused deterministic reduction
            spin_ctr(&g_chunk_done[(s * 8 + tile) * CSTR], nch);
            if (modeB) {
                if (tid < 64 && chunk < R_t) {
                    int row = tile * 64 + chunk, a = tid;
                    float ssum = 0.f;
                    #pragma unroll 16
                    for (int cc = 0; cc < 64; cc++)
                        ssum += __ldcg(&g_part[(size_t)((cc << 8) + row) * Kk + a]);
                    int cell = row >> 3, b = row & 7;
                    g_chart[cidx(cell, cell + s, b, a)] = ssum;
                }
            } else {
                if (tid < 128) {
                    int rl = chunk * 2 + (tid >> 6);
                    if (rl < R_t) {
                        int row = tile * 64 + rl, a = tid & 63;
                        float ssum = 0.f;
                        #pragma unroll 16
                        for (int cc = 0; cc < 32; cc++)
                            ssum += __ldcg(&g_part[(size_t)((cc << 9) + row) * Kk + a]);
                        int cell = row >> 3, b = row & 7;
                        g_chart[cidx(cell, cell + s, b, a)] = ssum;
                    }
                }
            }
            __syncthreads();
            if (tid == 0) {
                int old = atom_ar(&g_red_tile[(s * 8 + tile) * CSTR], 1);
                if (old == nch - 1) {
                    int t = atom_ar(&g_tiles_done[s * CSTR], 1);
                    if (t == ntiles - 1) publish_level(s);
                }
            }
        }

        // ---- A_pre(s+1): splits 2..s-1 into the other pair buffer
        if (s < Nn && s + 1 >= 4) {
            const int s2 = s + 1;
            const int rows2 = (Nn - s2 + 1) * Bb;
            float* const pairn = g_pair2[s2 & 1];
            for (int u = bid; u < rows2; u += nblk) {
                const int cell = u >> 3, b = u & 7;
                ull acc[4][2];
                #pragma unroll
                for (int i = 0; i < 4; i++) { acc[i][0] = 0ull; acc[i][1] = 0ull; }
                const float* Lbase = &g_chart[cidx(cell, cell, b, x0)];
                const float* Rbase = &g_chart[cidx(cell, cell + s2, b, y0r)];
                #pragma unroll 4
                for (int sp = 2; sp <= s2 - 2; sp++) {
                    float4 L = __ldcg((const float4*)(Lbase + (size_t)sp * (Bb * Kk)));
                    float4 R = __ldcg((const float4*)(Rbase + (size_t)sp * (NB1 * Bb * Kk)));
                    ull r01 = pack2(R.x, R.y), r23 = pack2(R.z, R.w);
                    ull l;
                    l = pack2(L.x, L.x); fma2(acc[0][0], l, r01); fma2(acc[0][1], l, r23);
                    l = pack2(L.y, L.y); fma2(acc[1][0], l, r01); fma2(acc[1][1], l, r23);
                    l = pack2(L.z, L.z); fma2(acc[2][0], l, r01); fma2(acc[2][1], l, r23);
                    l = pack2(L.w, L.w); fma2(acc[3][0], l, r01); fma2(acc[3][1], l, r23);
                }
                #pragma unroll
                for (int i = 0; i < 4; i++) {
                    float2 e0 = unpk(acc[i][0]), e1 = unpk(acc[i][1]);
                    float4 o; o.x = e0.x; o.y = e0.y; o.z = e1.x; o.w = e1.y;
                    *(float4*)&pairn[(size_t)u * KK2 + (x0 + i) * Kk + y0r] = o;
                }
                __syncthreads();
                if (tid == 0) red_rel(&g_pre_ready[(s2 * 8 + (u >> 6)) * CSTR], 1);
            }
        }
    }

    // ---- Final output
    if (bid == 0) {
        spin_level(0, Nn);
        if (w < Bb) {
            const int b = w;
            float p = 0.f;
            #pragma unroll
            for (int q = 0; q < 2; q++) {
                int a = lane + q * 32;
                p += prior[a] * __ldcg(&g_chart[cidx(0, Nn, b, a)]);
            }
            #pragma unroll
            for (int off = 16; off; off >>= 1) p += __shfl_down_sync(0xffffffffu, p, off);
            if (lane == 0) out[b] = p;
        }
    }

    // ---- End barrier + counter reset for next replay
    gbar(gen + 1, nblk);
    if (bid == 0) {
        for (int i = tid; i < NB1 * 8 * CSTR; i += 256) {
            g_pre_ready[i] = 0;
            g_chunk_done[i] = 0;
            g_red_tile[i] = 0;
        }
        for (int i = tid; i < NB1 * CSTR; i += 256) g_tiles_done[i] = 0;
        for (int i = tid; i < NLVL * CSTR; i += 256) g_lvl[i] = 0;
        for (int i = tid; i < 8 * CSTR; i += 256) g_c0[i] = 0;
        if (tid == 0) g_c0m = 0;
    }
}

extern "C" void kernel_launch(void* const* d_in, const int* in_sizes, int n_in,
                              void* d_out, int out_size)
{
    const float* seq   = (const float*)d_in[0];
    const float* rule  = (const float*)d_in[1];
    const float* emit  = (const float*)d_in[2];
    const float* prior = (const float*)d_in[3];
    float* out = (float*)d_out;

    cudaFuncSetAttribute(rbn_persistent, cudaFuncAttributeMaxDynamicSharedMemorySize, SMEM_BYTES);

    int dev = 0, nsm = 1;
    cudaGetDevice(&dev);
    cudaDeviceGetAttribute(&nsm, cudaDevAttrMultiProcessorCount, dev);
    int bpm = 1;
    cudaOccupancyMaxActiveBlocksPerMultiprocessor(&bpm, rbn_persistent, 256, SMEM_BYTES);
    if (bpm < 1) bpm = 1;
    if (bpm > 3) bpm = 3;
    int nblk = nsm * bpm;
    if (nblk > 444) nblk = 444;
    if (nblk < 256) nblk = 256;

    rbn_persistent<<<nblk, 256, SMEM_BYTES>>>(seq, rule, emit, prior, out, nblk);
}

// round 9
// speedup vs baseline: 1.2280x; 1.0240x over previous
#include <cuda_runtime.h>

#define Bb 8
#define Nn 64
#define Kk 64
#define Tt 128
#define NB1 65
#define KK2 4096
#define MAXROWS 512
#define SSTR 68
#define SMEM_BYTES (2 * 128 * SSTR * 4)   // 69632 -> 3 CTAs/SM
#define CSTR 32
#define NLVL 16

typedef unsigned long long ull;

__device__ __align__(256) float g_chart[NB1 * NB1 * Bb * Kk];
__device__ __align__(256) float g_pair2[2][MAXROWS * KK2];
__device__ __align__(256) float g_part[32 * MAXROWS * Kk];

__device__ int g_lvl[NLVL * CSTR];
__device__ int g_pre_ready[NB1 * 8 * CSTR];
__device__ int g_chunk_done[NB1 * 8 * CSTR];
__device__ int g_red_tile [NB1 * 8 * CSTR];
__device__ int g_tiles_done[NB1 * CSTR];
__device__ int g_c0[8 * CSTR];
__device__ int g_c0m;
__device__ unsigned g_arrive = 0;
__device__ unsigned g_release = 0;

__device__ __forceinline__ int cidx(int i, int j, int b, int k) {
    return ((i * NB1 + j) * Bb + b) * Kk + k;
}
__device__ __forceinline__ ull pack2(float lo, float hi) {
    ull r; asm("mov.b64 %0, {%1, %2};" : "=l"(r) : "f"(lo), "f"(hi)); return r;
}
__device__ __forceinline__ void fma2(ull& d, ull a, ull b) {
    asm("fma.rn.f32x2 %0, %1, %2, %0;" : "+l"(d) : "l"(a), "l"(b));
}
__device__ __forceinline__ float2 unpk(ull v) {
    float2 o; asm("mov.b64 {%0, %1}, %2;" : "=f"(o.x), "=f"(o.y) : "l"(v)); return o;
}
__device__ __forceinline__ int ld_acq(const int* p) {
    int v; asm volatile("ld.acquire.gpu.global.b32 %0, [%1];" : "=r"(v) : "l"(p) : "memory"); return v;
}
__device__ __forceinline__ void red_rel(int* p, int v) {
    asm volatile("red.release.gpu.global.add.s32 [%0], %1;" :: "l"(p), "r"(v) : "memory");
}
__device__ __forceinline__ int atom_ar(int* p, int v) {
    int o; asm volatile("atom.acq_rel.gpu.global.add.s32 %0, [%1], %2;" : "=r"(o) : "l"(p), "r"(v) : "memory"); return o;
}
__device__ __forceinline__ void st_rel(int* p, int v) {
    asm volatile("st.release.gpu.global.b32 [%0], %1;" :: "l"(p), "r"(v) : "memory");
}
__device__ __forceinline__ void publish_level(int s) {
    #pragma unroll
    for (int i = 0; i < NLVL; i++) st_rel(&g_lvl[i * CSTR], s);
}
__device__ __forceinline__ void spin_level(int slot, int target) {
    if (threadIdx.x == 0) {
        while (ld_acq(&g_lvl[slot * CSTR]) < target) { }
    }
    __syncthreads();
}
__device__ __forceinline__ void spin_ctr(int* p, int target) {
    if (threadIdx.x == 0) {
        while (ld_acq(p) < target) { }
    }
    __syncthreads();
}
__device__ __forceinline__ void gbar(unsigned target, int nblk) {
    __threadfence();
    __syncthreads();
    if (threadIdx.x == 0) {
        unsigned old = atomicAdd(&g_arrive, 1u);
        if (old == (unsigned)(nblk - 1)) {
            g_arrive = 0;
            __threadfence();
            *(volatile unsigned*)&g_release = target;
        } else {
            while ((int)(*(volatile unsigned*)&g_release - target) < 0) __nanosleep(64);
            __threadfence();
        }
    }
    __syncthreads();
}

__global__ void __launch_bounds__(256, 3)
rbn_persistent(const float* __restrict__ seq, const float* __restrict__ rule,
               const float* __restrict__ emit, const float* __restrict__ prior,
               float* __restrict__ out, int nblk)
{
    extern __shared__ float smem[];
    float* sA = smem;
    float* sB = smem + 128 * SSTR;

    const int tid = threadIdx.x;
    const int bid = blockIdx.x;
    const int w = tid >> 5, lane = tid & 31;
    const int tx = tid & 15, ty = tid >> 4;
    const int x0 = ty * 4, y0r = tx * 4;
    const int myslot = bid & (NLVL - 1);

    const unsigned gen = *(volatile unsigned*)&g_release;

    // ---- Phase 0: span-1 cells (distributed completion counters, tight)
    for (int u = bid; u < Nn * Bb; u += nblk) {
        int i = u >> 3, b = u & 7;
        const float* srow = seq + (b * Nn + i) * Tt;
        #pragma unroll
        for (int aa = 0; aa < 8; aa++) {
            int a = w * 8 + aa;
            float p = 0.f;
            #pragma unroll
            for (int q = 0; q < 4; q++) {
                int t2 = lane + q * 32;
                p += emit[a * Tt + t2] * srow[t2];
            }
            #pragma unroll
            for (int off = 16; off; off >>= 1) p += __shfl_down_sync(0xffffffffu, p, off);
            if (lane == 0) g_chart[cidx(i, i + 1, b, a)] = p;
        }
        __syncthreads();
        if (tid == 0) {
            int old = atom_ar(&g_c0[(u & 7) * CSTR], 1);
            if (old == (Nn * Bb / 8) - 1) {
                int mo = atom_ar(&g_c0m, 1);
                if (mo == 7) publish_level(1);
            }
        }
    }

    for (int s = 2; s <= Nn; s++) {
        const int m = Nn - s + 1;
        const int rows = m * Bb;
        const int ntiles = (rows + 63) >> 6;
        const int nunits = ntiles * 32;          // nch=32, ck=128 always
        float* const pairc = g_pair2[s & 1];

        int tile = 0, chunk = 0, kbase = 0, R_t = 0;
        const int lr = tid >> 2, lq = tid & 3;
        if (bid < nunits) {
            tile  = bid >> 5;
            chunk = bid & 31;
            kbase = chunk * 128;
            R_t = min(64, rows - tile * 64);
            // prefetch rule slice (constant) into sB before any gate
            const float4* pb = (const float4*)&rule[(size_t)lr * KK2 + kbase + lq * 4];
            #pragma unroll
            for (int kb = 0; kb < 128; kb += 16) {
                float4 vb = pb[kb >> 2];
                int kk = kb + lq * 4;
                sB[(kk + 0) * SSTR + lr] = vb.x;
                sB[(kk + 1) * SSTR + lr] = vb.y;
                sB[(kk + 2) * SSTR + lr] = vb.z;
                sB[(kk + 3) * SSTR + lr] = vb.w;
            }
        }

        spin_level(myslot, s - 1);

        if (bid < nunits) {
            if (s >= 4) spin_ctr(&g_pre_ready[(s * 8 + tile) * CSTR], R_t);

            // ---- stage sA = pairc + split{1} + split{s-1} (fused A_final)
            {
                const int row = tile * 64 + lr;
                const int cell = row >> 3, b = row & 7;
                const float* L1row = &g_chart[cidx(cell, cell + 1, b, 0)];
                const float* R1row = &g_chart[cidx(cell + 1, cell + s, b, 0)];
                const float* L2row = &g_chart[cidx(cell, cell + s - 1, b, 0)];
                const float* R2row = &g_chart[cidx(cell + s - 1, cell + s, b, 0)];
                const float4* pa = (const float4*)&pairc[(size_t)row * KK2 + kbase + lq * 4];
                #pragma unroll 2
                for (int kb = 0; kb < 128; kb += 16) {
                    const int kk = kb + lq * 4;
                    const int kg = kbase + kk;
                    const int xx = kg >> 6, yy = kg & 63;
                    float4 va;
                    if (s >= 4) va = __ldcg(pa + (kb >> 2));
                    else { va.x = 0.f; va.y = 0.f; va.z = 0.f; va.w = 0.f; }
                    {
                        float l1 = __ldcg(L1row + xx);
                        float4 r1 = __ldcg((const float4*)(R1row + yy));
                        va.x += l1 * r1.x; va.y += l1 * r1.y;
                        va.z += l1 * r1.z; va.w += l1 * r1.w;
                    }
                    if (s >= 3) {
                        float l2 = __ldcg(L2row + xx);
                        float4 r2 = __ldcg((const float4*)(R2row + yy));
                        va.x += l2 * r2.x; va.y += l2 * r2.y;
                        va.z += l2 * r2.z; va.w += l2 * r2.w;
                    }
                    sA[(kk + 0) * SSTR + lr] = va.x;
                    sA[(kk + 1) * SSTR + lr] = va.y;
                    sA[(kk + 2) * SSTR + lr] = va.z;
                    sA[(kk + 3) * SSTR + lr] = va.w;
                }
            }
            __syncthreads();

            // ---- GEMM: 64x64 x 128
            ull acc[4][2];
            #pragma unroll
            for (int i = 0; i < 4; i++) { acc[i][0] = 0ull; acc[i][1] = 0ull; }
            #pragma unroll 8
            for (int k = 0; k < 128; k++) {
                float4 av = *(const float4*)&sA[k * SSTR + x0];
                float4 bv = *(const float4*)&sB[k * SSTR + y0r];
                ull b01 = pack2(bv.x, bv.y), b23 = pack2(bv.z, bv.w);
                ull a2;
                a2 = pack2(av.x, av.x); fma2(acc[0][0], a2, b01); fma2(acc[0][1], a2, b23);
                a2 = pack2(av.y, av.y); fma2(acc[1][0], a2, b01); fma2(acc[1][1], a2, b23);
                a2 = pack2(av.z, av.z); fma2(acc[2][0], a2, b01); fma2(acc[2][1], a2, b23);
                a2 = pack2(av.w, av.w); fma2(acc[3][0], a2, b01); fma2(acc[3][1], a2, b23);
            }
            #pragma unroll
            for (int i = 0; i < 4; i++) {
                int row = tile * 64 + x0 + i;
                int base = (chunk << 9) + row;
                float2 e0 = unpk(acc[i][0]), e1 = unpk(acc[i][1]);
                float4 o; o.x = e0.x; o.y = e0.y; o.z = e1.x; o.w = e1.y;
                *(float4*)&g_part[(size_t)base * Kk + y0r] = o;
            }
            __syncthreads();
            if (tid == 0) red_rel(&g_chunk_done[(s * 8 + tile) * CSTR], 1);

            // ---- fused deterministic reduction (2 rows/chunk)
            spin_ctr(&g_chunk_done[(s * 8 + tile) * CSTR], 32);
            if (tid < 128) {
                int rl = chunk * 2 + (tid >> 6);
                if (rl < R_t) {
                    int row = tile * 64 + rl, a = tid & 63;
                    float ssum = 0.f;
                    #pragma unroll 16
                    for (int cc = 0; cc < 32; cc++)
                        ssum += __ldcg(&g_part[(size_t)((cc << 9) + row) * Kk + a]);
                    int cell = row >> 3, b = row & 7;
                    g_chart[cidx(cell, cell + s, b, a)] = ssum;
                }
            }
            __syncthreads();
            if (tid == 0) {
                int old = atom_ar(&g_red_tile[(s * 8 + tile) * CSTR], 1);
                if (old == 31) {
                    if (ntiles == 1) {
                        publish_level(s);
                    } else {
                        int t = atom_ar(&g_tiles_done[s * CSTR], 1);
                        if (t == ntiles - 1) publish_level(s);
                    }
                }
            }
        }

        // ---- A_pre(s+1): splits 2..s-1, rotated so free CTAs take rows first
        if (s < Nn && s + 1 >= 4) {
            const int s2 = s + 1;
            const int rows2 = (Nn - s2 + 1) * Bb;
            float* const pairn = g_pair2[s2 & 1];
            int u0 = bid - nunits; if (u0 < 0) u0 += nblk;
            for (int u = u0; u < rows2; u += nblk) {
                const int cell = u >> 3, b = u & 7;
                ull acc[4][2];
                #pragma unroll
                for (int i = 0; i < 4; i++) { acc[i][0] = 0ull; acc[i][1] = 0ull; }
                const float* Lbase = &g_chart[cidx(cell, cell, b, x0)];
                const float* Rbase = &g_chart[cidx(cell, cell + s2, b, y0r)];
                #pragma unroll 4
                for (int sp = 2; sp <= s2 - 2; sp++) {
                    float4 L = __ldcg((const float4*)(Lbase + (size_t)sp * (Bb * Kk)));
                    float4 R = __ldcg((const float4*)(Rbase + (size_t)sp * (NB1 * Bb * Kk)));
                    ull r01 = pack2(R.x, R.y), r23 = pack2(R.z, R.w);
                    ull l;
                    l = pack2(L.x, L.x); fma2(acc[0][0], l, r01); fma2(acc[0][1], l, r23);
                    l = pack2(L.y, L.y); fma2(acc[1][0], l, r01); fma2(acc[1][1], l, r23);
                    l = pack2(L.z, L.z); fma2(acc[2][0], l, r01); fma2(acc[2][1], l, r23);
                    l = pack2(L.w, L.w); fma2(acc[3][0], l, r01); fma2(acc[3][1], l, r23);
                }
                #pragma unroll
                for (int i = 0; i < 4; i++) {
                    float2 e0 = unpk(acc[i][0]), e1 = unpk(acc[i][1]);
                    float4 o; o.x = e0.x; o.y = e0.y; o.z = e1.x; o.w = e1.y;
                    *(float4*)&pairn[(size_t)u * KK2 + (x0 + i) * Kk + y0r] = o;
                }
                __syncthreads();
                if (tid == 0) red_rel(&g_pre_ready[(s2 * 8 + (u >> 6)) * CSTR], 1);
            }
        }
    }

    // ---- Final output
    if (bid == 0) {
        spin_level(0, Nn);
        if (w < Bb) {
            const int b = w;
            float p = 0.f;
            #pragma unroll
            for (int q = 0; q < 2; q++) {
                int a = lane + q * 32;
                p += prior[a] * __ldcg(&g_chart[cidx(0, Nn, b, a)]);
            }
            #pragma unroll
            for (int off = 16; off; off >>= 1) p += __shfl_down_sync(0xffffffffu, p, off);
            if (lane == 0) out[b] = p;
        }
    }

    // ---- End barrier + counter reset for next replay
    gbar(gen + 1, nblk);
    if (bid == 0) {
        for (int i = tid; i < NB1 * 8 * CSTR; i += 256) {
            g_pre_ready[i] = 0;
            g_chunk_done[i] = 0;
            g_red_tile[i] = 0;
        }
        for (int i = tid; i < NB1 * CSTR; i += 256) g_tiles_done[i] = 0;
        for (int i = tid; i < NLVL * CSTR; i += 256) g_lvl[i] = 0;
        for (int i = tid; i < 8 * CSTR; i += 256) g_c0[i] = 0;
        if (tid == 0) g_c0m = 0;
    }
}

extern "C" void kernel_launch(void* const* d_in, const int* in_sizes, int n_in,
                              void* d_out, int out_size)
{
    const float* seq   = (const float*)d_in[0];
    const float* rule  = (const float*)d_in[1];
    const float* emit  = (const float*)d_in[2];
    const float* prior = (const float*)d_in[3];
    float* out = (float*)d_out;

    cudaFuncSetAttribute(rbn_persistent, cudaFuncAttributeMaxDynamicSharedMemorySize, SMEM_BYTES);

    int dev = 0, nsm = 1;
    cudaGetDevice(&dev);
    cudaDeviceGetAttribute(&nsm, cudaDevAttrMultiProcessorCount, dev);
    int bpm = 1;
    cudaOccupancyMaxActiveBlocksPerMultiprocessor(&bpm, rbn_persistent, 256, SMEM_BYTES);
    if (bpm < 1) bpm = 1;
    if (bpm > 3) bpm = 3;
    int nblk = nsm * bpm;
    if (nblk > 444) nblk = 444;
    if (nblk < 256) nblk = 256;

    rbn_persistent<<<nblk, 256, SMEM_BYTES>>>(seq, rule, emit, prior, out, nblk);
}

// round 10
// speedup vs baseline: 1.5526x; 1.2643x over previous
#include <cuda_runtime.h>

#define Bb 8
#define Nn 64
#define Kk 64
#define Tt 128
#define NB1 65
#define KK2 4096
#define SSTR 68
#define SMEM_BYTES (2 * 128 * SSTR * 4)   // 69632 -> 3 CTAs/SM
#define CSTR 32
#define NF 64

typedef unsigned long long ull;

__device__ __align__(256) float g_chart[NB1 * NB1 * Bb * Kk];
__device__ __align__(256) float g_pairs[2][512 * KK2];
__device__ __align__(256) float g_part[2][8][32][64 * 64];
__device__ __align__(256) float g_vpre[2][512 * 64];
__device__ __align__(256) float g_U1[512 * 4096];
__device__ __align__(256) float g_V2[512 * 4096];
__device__ __align__(256) float g_rT[64 * 4096];   // rT[x][y*64+a]  = rule[a][x][y]
__device__ __align__(256) float g_rT2[64 * 4096];  // rT2[y][x*64+a] = rule[a][x][y]

__device__ int g_lvl;
__device__ int g_pre_ready[NB1 * 8 * CSTR];
__device__ int g_chunkdone[NB1 * 8 * CSTR];
__device__ int g_gdone[NB1 * CSTR];
__device__ int g_fgrp[NB1 * 8 * CSTR];
__device__ int g_fmst[NB1 * CSTR];
__device__ int g_c0[8 * CSTR];
__device__ int g_c0m;
__device__ int g_rt;
__device__ int g_uv;
__device__ unsigned g_arrive = 0;
__device__ unsigned g_release = 0;

__device__ __forceinline__ int cidx(int i, int j, int b, int k) {
    return ((i * NB1 + j) * Bb + b) * Kk + k;
}
__device__ __forceinline__ ull pack2(float lo, float hi) {
    ull r; asm("mov.b64 %0, {%1, %2};" : "=l"(r) : "f"(lo), "f"(hi)); return r;
}
__device__ __forceinline__ void fma2(ull& d, ull a, ull b) {
    asm("fma.rn.f32x2 %0, %1, %2, %0;" : "+l"(d) : "l"(a), "l"(b));
}
__device__ __forceinline__ float2 unpk(ull v) {
    float2 o; asm("mov.b64 {%0, %1}, %2;" : "=f"(o.x), "=f"(o.y) : "l"(v)); return o;
}
__device__ __forceinline__ int ld_acq(const int* p) {
    int v; asm volatile("ld.acquire.gpu.global.b32 %0, [%1];" : "=r"(v) : "l"(p) : "memory"); return v;
}
__device__ __forceinline__ void red_rel(int* p, int v) {
    asm volatile("red.release.gpu.global.add.s32 [%0], %1;" :: "l"(p), "r"(v) : "memory");
}
__device__ __forceinline__ int atom_ar(int* p, int v) {
    int o; asm volatile("atom.acq_rel.gpu.global.add.s32 %0, [%1], %2;" : "=r"(o) : "l"(p), "r"(v) : "memory"); return o;
}
__device__ __forceinline__ void st_rel(int* p, int v) {
    asm volatile("st.release.gpu.global.b32 [%0], %1;" :: "l"(p), "r"(v) : "memory");
}
__device__ __forceinline__ void spin_ctr(int* p, int target) {
    if (threadIdx.x == 0) { while (ld_acq(p) < target) { } }
    __syncthreads();
}
__device__ __forceinline__ void spin_lvl(int target) {
    if (threadIdx.x == 0) { while (ld_acq(&g_lvl) < target) { } }
    __syncthreads();
}
__device__ __forceinline__ int units_of(int s) {
    int m = 65 - s;
    return ((m + 7) >> 3) * 32;
}
__device__ __forceinline__ void gbar(unsigned target, int nblk) {
    __threadfence();
    __syncthreads();
    if (threadIdx.x == 0) {
        unsigned old = atomicAdd(&g_arrive, 1u);
        if (old == (unsigned)(nblk - 1)) {
            g_arrive = 0;
            __threadfence();
            *(volatile unsigned*)&g_release = target;
        } else {
            while ((int)(*(volatile unsigned*)&g_release - target) < 0) __nanosleep(64);
            __threadfence();
        }
    }
    __syncthreads();
}

__global__ void __launch_bounds__(256, 3)
rbn_persistent(const float* __restrict__ seq, const float* __restrict__ rule,
               const float* __restrict__ emit, const float* __restrict__ prior,
               float* __restrict__ out, int nblk)
{
    extern __shared__ float smem[];
    const int tid = threadIdx.x;
    const int bid = blockIdx.x;
    const int w = tid >> 5, lane = tid & 31;
    const unsigned gen = *(volatile unsigned*)&g_release;

    // ================= Phase 0: span-1 cells (all CTAs) =================
    for (int u = bid; u < Nn * Bb; u += nblk) {
        int i = u >> 3, b = u & 7;
        const float* srow = seq + (b * Nn + i) * Tt;
        #pragma unroll
        for (int aa = 0; aa < 8; aa++) {
            int a = w * 8 + aa;
            float p = 0.f;
            #pragma unroll
            for (int q = 0; q < 4; q++) {
                int t2 = lane + q * 32;
                p += emit[a * Tt + t2] * srow[t2];
            }
            #pragma unroll
            for (int off = 16; off; off >>= 1) p += __shfl_down_sync(0xffffffffu, p, off);
            if (lane == 0) g_chart[cidx(i, i + 1, b, a)] = p;
        }
        __syncthreads();
        if (tid == 0) {
            int old = atom_ar(&g_c0[(u & 7) * CSTR], 1);
            if (old == (Nn * Bb / 8) - 1) {
                int mo = atom_ar(&g_c0m, 1);
                if (mo == 7) st_rel(&g_lvl, 1);
            }
        }
    }

    if (bid < NF) {
        // ================= FRONT CTAs: the latency chain =================
        const int f = bid;
        float* sR1 = smem;            // [4][64]
        float* sL2 = smem + 256;      // [4][64]
        if (f <= 62) {
            spin_ctr(&g_uv, 256);     // U1/V2 ready
            for (int s = 2; s <= Nn - f; s++) {
                const int m = 65 - s;
                spin_lvl(s - 1);
                if (s >= 4) spin_ctr(&g_gdone[s * CSTR], units_of(s));

                #pragma unroll
                for (int p = 0; p < 2; p++) {
                    const int rg = tid >> 6, a = tid & 63;
                    const int b = p * 4 + rg;
                    sR1[rg * 64 + a] = __ldcg(&g_chart[cidx(f + 1, f + s, b, a)]);
                    if (s >= 3) sL2[rg * 64 + a] = __ldcg(&g_chart[cidx(f, f + s - 1, b, a)]);
                    __syncthreads();
                    float acc = (s >= 4) ? __ldcg(&g_vpre[s & 1][((f * 8 + b) << 6) + a]) : 0.f;
                    {
                        const float* u1 = &g_U1[(size_t)(f * 8 + b) << 12];
                        #pragma unroll 16
                        for (int y = 0; y < 64; y++)
                            acc += u1[y * 64 + a] * sR1[rg * 64 + y];
                    }
                    if (s >= 3) {
                        const float* v2 = &g_V2[(size_t)((f + s - 1) * 8 + b) << 12];
                        #pragma unroll 16
                        for (int x = 0; x < 64; x++)
                            acc += v2[x * 64 + a] * sL2[rg * 64 + x];
                    }
                    g_chart[cidx(f, f + s, b, a)] = acc;
                    __syncthreads();
                }
                if (tid == 0) {
                    int g = f >> 3;
                    int ngroups = (m + 7) >> 3;
                    int ga = min(8, m - g * 8);
                    int old = atom_ar(&g_fgrp[(s * 8 + g) * CSTR], 1);
                    if (old == ga - 1) {
                        int o2 = atom_ar(&g_fmst[s * CSTR], 1);
                        if (o2 == ngroups - 1) st_rel(&g_lvl, s);
                    }
                }
            }
        }
        if (bid == 0) {
            spin_lvl(Nn);
            if (w < Bb) {
                const int b = w;
                float p = 0.f;
                #pragma unroll
                for (int q = 0; q < 2; q++) {
                    int a = lane + q * 32;
                    p += prior[a] * __ldcg(&g_chart[cidx(0, Nn, b, a)]);
                }
                #pragma unroll
                for (int off = 16; off; off >>= 1) p += __shfl_down_sync(0xffffffffu, p, off);
                if (lane == 0) out[b] = p;
            }
        }
    } else {
        // ================= BACKGROUND CTAs =================
        const int j = bid - NF;
        const int nbg = nblk - NF;
        const int tx = tid & 15, ty = tid >> 4;
        const int x0 = ty * 4, y0r = tx * 4;
        float* sA = smem;
        float* sB = smem + 128 * SSTR;

        // ---- build rule transposes (64 units)
        for (int u = j; u < 64; u += nbg) {
            for (int idx = tid; idx < 4096; idx += 256) {
                int c1 = idx >> 6, a = idx & 63;
                float v = rule[(size_t)a * KK2 + u * 64 + c1];   // rule[a][u][c1]
                g_rT[(size_t)u * 4096 + c1 * 64 + a] = v;        // rT[x=u][y=c1][a]
                float v2 = rule[(size_t)a * KK2 + c1 * 64 + u];  // rule[a][c1][u]
                g_rT2[(size_t)u * 4096 + c1 * 64 + a] = v2;      // rT2[y=u][x=c1][a]
            }
            __syncthreads();
            if (tid == 0) red_rel(&g_rt, 1);
        }
        spin_lvl(1);
        spin_ctr(&g_rt, 64);

        // ---- precompute U1 / V2 (GEMM form, 256 units)
        {
            float* sRT = smem;          // 64 x 256 = 64KB
            float* sC1 = smem + 16384;  // 16 x 64  = 4KB
            for (int u = j; u < 256; u += nbg) {
                const int isV = (u >= 128);
                const int uu = u & 127;
                const int rt = uu >> 4, cc = uu & 15;
                const float* RT = isV ? g_rT2 : g_rT;
                float* OUT = isV ? g_V2 : g_U1;
                for (int idx = tid; idx < 16384; idx += 256) {
                    int xx = idx >> 8, c = idx & 255;
                    sRT[idx] = RT[(size_t)xx * 4096 + cc * 256 + c];
                }
                __syncthreads();
                for (int rblk = 0; rblk < 4; rblk++) {
                    for (int idx = tid; idx < 1024; idx += 256) {
                        int rr = idx >> 6, xx = idx & 63;
                        int row = rt * 64 + rblk * 16 + rr;
                        sC1[idx] = __ldcg(&g_chart[cidx(row >> 3, (row >> 3) + 1, row & 7, xx)]);
                    }
                    __syncthreads();
                    for (int rr = 0; rr < 16; rr++) {
                        int row = rt * 64 + rblk * 16 + rr;
                        float acc = 0.f;
                        #pragma unroll 8
                        for (int xx = 0; xx < 64; xx++)
                            acc += sC1[rr * 64 + xx] * sRT[xx * 256 + tid];
                        OUT[(size_t)row * 4096 + cc * 256 + tid] = acc;
                    }
                    __syncthreads();
                }
                if (tid == 0) red_rel(&g_uv, 1);
            }
        }

        // ---- main background pipeline: A_pre(s2) then GEMM(s2)
        for (int s2 = 4; s2 <= Nn; s2++) {
            const int m2 = 65 - s2;
            const int rows2 = m2 * Bb;
            const int units = units_of(s2);
            float* const pairn = g_pairs[s2 & 1];

            // A_pre: splits 2..s2-2, gated on level s2-2
            spin_lvl(s2 - 2);
            for (int u = j; u < rows2; u += nbg) {
                const int cell = u >> 3, b = u & 7;
                ull acc[4][2];
                #pragma unroll
                for (int i = 0; i < 4; i++) { acc[i][0] = 0ull; acc[i][1] = 0ull; }
                const float* Lbase = &g_chart[cidx(cell, cell, b, x0)];
                const float* Rbase = &g_chart[cidx(cell, cell + s2, b, y0r)];
                #pragma unroll 4
                for (int sp = 2; sp <= s2 - 2; sp++) {
                    float4 L = __ldcg((const float4*)(Lbase + (size_t)sp * (Bb * Kk)));
                    float4 R = __ldcg((const float4*)(Rbase + (size_t)sp * (NB1 * Bb * Kk)));
                    ull r01 = pack2(R.x, R.y), r23 = pack2(R.z, R.w);
                    ull l;
                    l = pack2(L.x, L.x); fma2(acc[0][0], l, r01); fma2(acc[0][1], l, r23);
                    l = pack2(L.y, L.y); fma2(acc[1][0], l, r01); fma2(acc[1][1], l, r23);
                    l = pack2(L.z, L.z); fma2(acc[2][0], l, r01); fma2(acc[2][1], l, r23);
                    l = pack2(L.w, L.w); fma2(acc[3][0], l, r01); fma2(acc[3][1], l, r23);
                }
                #pragma unroll
                for (int i = 0; i < 4; i++) {
                    float2 e0 = unpk(acc[i][0]), e1 = unpk(acc[i][1]);
                    float4 o; o.x = e0.x; o.y = e0.y; o.z = e1.x; o.w = e1.y;
                    *(float4*)&pairn[(size_t)u * KK2 + (x0 + i) * Kk + y0r] = o;
                }
                __syncthreads();
                if (tid == 0) red_rel(&g_pre_ready[(s2 * 8 + (u >> 6)) * CSTR], 1);
            }

            // GEMM + reduce (units <= 256)
            if (j < units) {
                const int tile = j >> 5;
                const int chunk = j & 31;
                const int kbase = chunk * 128;
                const int R_t = min(64, rows2 - tile * 64);
                const int lr = tid >> 2, lq = tid & 3;

                // stage rule slice (immutable) while waiting is unnecessary; just gate then stage
                if (s2 >= 6) spin_ctr(&g_gdone[(s2 - 2) * CSTR], units_of(s2 - 2));
                spin_ctr(&g_pre_ready[(s2 * 8 + tile) * CSTR], R_t);

                {
                    const float4* pb = (const float4*)&rule[(size_t)lr * KK2 + kbase + lq * 4];
                    const float4* pa = (const float4*)&pairn[(size_t)(tile * 64 + lr) * KK2 + kbase + lq * 4];
                    #pragma unroll
                    for (int kb = 0; kb < 128; kb += 16) {
                        float4 vb = pb[kb >> 2];
                        float4 va = __ldcg(pa + (kb >> 2));
                        int kk = kb + lq * 4;
                        sB[(kk + 0) * SSTR + lr] = vb.x;
                        sB[(kk + 1) * SSTR + lr] = vb.y;
                        sB[(kk + 2) * SSTR + lr] = vb.z;
                        sB[(kk + 3) * SSTR + lr] = vb.w;
                        sA[(kk + 0) * SSTR + lr] = va.x;
                        sA[(kk + 1) * SSTR + lr] = va.y;
                        sA[(kk + 2) * SSTR + lr] = va.z;
                        sA[(kk + 3) * SSTR + lr] = va.w;
                    }
                }
                __syncthreads();

                ull acc[4][2];
                #pragma unroll
                for (int i = 0; i < 4; i++) { acc[i][0] = 0ull; acc[i][1] = 0ull; }
                #pragma unroll 8
                for (int k = 0; k < 128; k++) {
                    float4 av = *(const float4*)&sA[k * SSTR + x0];
                    float4 bv = *(const float4*)&sB[k * SSTR + y0r];
                    ull b01 = pack2(bv.x, bv.y), b23 = pack2(bv.z, bv.w);
                    ull a2;
                    a2 = pack2(av.x, av.x); fma2(acc[0][0], a2, b01); fma2(acc[0][1], a2, b23);
                    a2 = pack2(av.y, av.y); fma2(acc[1][0], a2, b01); fma2(acc[1][1], a2, b23);
                    a2 = pack2(av.z, av.z); fma2(acc[2][0], a2, b01); fma2(acc[2][1], a2, b23);
                    a2 = pack2(av.w, av.w); fma2(acc[3][0], a2, b01); fma2(acc[3][1], a2, b23);
                }
                float* part = &g_part[s2 & 1][tile][chunk][0];
                #pragma unroll
                for (int i = 0; i < 4; i++) {
                    float2 e0 = unpk(acc[i][0]), e1 = unpk(acc[i][1]);
                    float4 o; o.x = e0.x; o.y = e0.y; o.z = e1.x; o.w = e1.y;
                    *(float4*)&part[(x0 + i) * 64 + y0r] = o;
                }
                __syncthreads();
                if (tid == 0) red_rel(&g_chunkdone[(s2 * 8 + tile) * CSTR], 1);

                spin_ctr(&g_chunkdone[(s2 * 8 + tile) * CSTR], 32);
                if (tid < 128) {
                    int rloc = chunk * 2 + (tid >> 6);
                    int row = tile * 64 + rloc;
                    if (row < rows2) {
                        int a = tid & 63;
                        float ssum = 0.f;
                        #pragma unroll 16
                        for (int cc = 0; cc < 32; cc++)
                            ssum += __ldcg(&g_part[s2 & 1][tile][cc][rloc * 64 + a]);
                        g_vpre[s2 & 1][(row << 6) + a] = ssum;
                    }
                }
                __syncthreads();
                if (tid == 0) red_rel(&g_gdone[s2 * CSTR], 1);
            }
        }
    }

    // ================= End barrier + counter reset for next replay =================
    gbar(gen + 1, nblk);
    if (bid == 0) {
        for (int i = tid; i < NB1 * 8 * CSTR; i += 256) {
            g_pre_ready[i] = 0;
            g_chunkdone[i] = 0;
            g_fgrp[i] = 0;
        }
        for (int i = tid; i < NB1 * CSTR; i += 256) { g_gdone[i] = 0; g_fmst[i] = 0; }
        for (int i = tid; i < 8 * CSTR; i += 256) g_c0[i] = 0;
        if (tid == 0) { g_c0m = 0; g_rt = 0; g_uv = 0; g_lvl = 0; }
    }
}

extern "C" void kernel_launch(void* const* d_in, const int* in_sizes, int n_in,
                              void* d_out, int out_size)
{
    const float* seq   = (const float*)d_in[0];
    const float* rule  = (const float*)d_in[1];
    const float* emit  = (const float*)d_in[2];
    const float* prior = (const float*)d_in[3];
    float* out = (float*)d_out;

    cudaFuncSetAttribute(rbn_persistent, cudaFuncAttributeMaxDynamicSharedMemorySize, SMEM_BYTES);

    int dev = 0, nsm = 1;
    cudaGetDevice(&dev);
    cudaDeviceGetAttribute(&nsm, cudaDevAttrMultiProcessorCount, dev);
    int bpm = 1;
    cudaOccupancyMaxActiveBlocksPerMultiprocessor(&bpm, rbn_persistent, 256, SMEM_BYTES);
    if (bpm < 1) bpm = 1;
    if (bpm > 3) bpm = 3;
    int nblk = nsm * bpm;
    if (nblk > 444) nblk = 444;
    if (nblk < 320) nblk = 320;   // NF(64) + 256 GEMM units must be co-resident

    rbn_persistent<<<nblk, 256, SMEM_BYTES>>>(seq, rule, emit, prior, out, nblk);
}